// round 14
// baseline (speedup 1.0000x reference)
#include <cuda_runtime.h>
#include <cuda_bf16.h>
#include <cstdint>

#define BATCH 64
#define SEQT  512
#define HID   1024
#define G3    3072            // 3*H
#define MROWS 32768           // B*T
#define KP3   3072            // 3*K split-concat (weights, big GEMM B operand)
#define KP2   2048            // 2*K split (activations + recurrent hidden)

// ---------------- device scratch (no allocations allowed) ----------------
__device__ __nv_bfloat16 g_Abig[(size_t)MROWS * KP2];   // split activations [hi|lo]
__device__ __nv_bfloat16 g_Wih0s[(size_t)G3 * KP3];
__device__ __nv_bfloat16 g_Wih1s[(size_t)G3 * KP3];
__device__ float         g_xg[(size_t)MROWS * G3];      // input-gate preactivations
__device__ float         g_y0[(size_t)MROWS * HID];     // layer0 outputs
__device__ float         g_hprev[2][BATCH * HID];
__device__ __nv_bfloat16 g_hs[2][BATCH * KP2];          // ping-pong split hidden
__device__ unsigned      g_barrier[2];                  // per-layer step barrier

// ---------------- helpers ----------------
__device__ __forceinline__ void mma_bf16(float c[4], const unsigned a[4], const unsigned b[2]) {
    asm volatile(
        "mma.sync.aligned.m16n8k16.row.col.f32.bf16.bf16.f32 "
        "{%0,%1,%2,%3}, {%4,%5,%6,%7}, {%8,%9}, {%0,%1,%2,%3};\n"
        : "+f"(c[0]), "+f"(c[1]), "+f"(c[2]), "+f"(c[3])
        : "r"(a[0]), "r"(a[1]), "r"(a[2]), "r"(a[3]), "r"(b[0]), "r"(b[1]));
}

__device__ __forceinline__ void cp16(uint32_t saddr, const void* gptr) {
    asm volatile("cp.async.cg.shared.global [%0], [%1], 16;\n"
                 :: "r"(saddr), "l"(gptr));
}

// activations: out = [hi | lo] (2048-wide) into g_Abig. use_y0: read g_y0.
__global__ void split2a_kernel(const float* __restrict__ src, int use_y0)
{
    const float* in = use_y0 ? g_y0 : src;
    int total = MROWS * HID;
    for (int i = blockIdx.x * blockDim.x + threadIdx.x; i < total;
         i += gridDim.x * blockDim.x) {
        int r = i >> 10;
        int c = i & 1023;
        float v = in[i];
        __nv_bfloat16 hi = __float2bfloat16(v);
        __nv_bfloat16 lo = __float2bfloat16(v - __bfloat162float(hi));
        __nv_bfloat16* o = g_Abig + (size_t)r * KP2;
        o[c] = hi; o[HID + c] = lo;
    }
}

// weights: out = [hi | lo | hi] (3072-wide). dst_sel: 1 -> g_Wih0s, 2 -> g_Wih1s.
__global__ void split3w_kernel(const float* __restrict__ src, int dst_sel)
{
    __nv_bfloat16* out = (dst_sel == 1) ? g_Wih0s : g_Wih1s;
    int total = G3 * HID;
    for (int i = blockIdx.x * blockDim.x + threadIdx.x; i < total;
         i += gridDim.x * blockDim.x) {
        int r = i >> 10;
        int c = i & 1023;
        float v = src[i];
        __nv_bfloat16 hi = __float2bfloat16(v);
        __nv_bfloat16 lo = __float2bfloat16(v - __bfloat162float(hi));
        __nv_bfloat16* o = out + (size_t)r * KP3;
        o[c] = hi; o[HID + c] = lo; o[2 * HID + c] = hi;
    }
}

__global__ void hinit_kernel(const float* __restrict__ h0, int layer)
{
    if (blockIdx.x == 0 && threadIdx.x == 0) g_barrier[layer] = 0;
    int i = blockIdx.x * blockDim.x + threadIdx.x;
    if (i < BATCH * HID) {
        float v = h0[i];
        g_hprev[layer][i] = v;
        __nv_bfloat16 hi = __float2bfloat16(v);
        __nv_bfloat16 lo = __float2bfloat16(v - __bfloat162float(hi));
        int b = i >> 10, j = i & 1023;
        g_hs[0][b * KP2 + j] = hi;
        g_hs[0][b * KP2 + HID + j] = lo;
    }
}

__global__ void tail_kernel(float* __restrict__ out)
{
    int i = blockIdx.x * blockDim.x + threadIdx.x;
    if (i < 2 * BATCH * HID) {
        int layer = i / (BATCH * HID);
        int r = i - layer * (BATCH * HID);
        out[i] = g_hprev[layer][r];
    }
}

// ---------------- big GEMM: g_xg = A'[M,3K] * W'[N,3K]^T + bias ----------------
// A' is virtual: seg0,1 -> hi (cols 0..1023 of g_Abig), seg2 -> lo (cols 1024..2047)
#define GBM 128
#define GBN 128
#define GBK 32
#define GLD 40      // BK + 8 bf16 pad (conflict-free, 16B-aligned rows)
#define GSTAGES 3
#define GSTAGE_ELEMS ((GBM + GBN) * GLD)   // 10240 bf16 per stage

__global__ __launch_bounds__(256, 2) void gemm_big_kernel(int wsel, const float* __restrict__ bias)
{
    extern __shared__ __nv_bfloat16 gsm[];
    const __nv_bfloat16* A = g_Abig;
    const __nv_bfloat16* B = wsel ? g_Wih1s : g_Wih0s;
    float* C = g_xg;
    const int N = G3;

    int tid = threadIdx.x;
    int bn = blockIdx.x, bm = blockIdx.y;

    int s0 = tid, s1 = tid + 256;
    int ar0 = s0 >> 2, ac0 = (s0 & 3) << 3;
    int ar1 = s1 >> 2, ac1 = (s1 & 3) << 3;

    const __nv_bfloat16* Ag0 = A + (size_t)(bm * GBM + ar0) * KP2 + ac0;
    const __nv_bfloat16* Ag1 = A + (size_t)(bm * GBM + ar1) * KP2 + ac1;
    const __nv_bfloat16* Bg0 = B + (size_t)(bn * GBN + ar0) * KP3 + ac0;
    const __nv_bfloat16* Bg1 = B + (size_t)(bn * GBN + ar1) * KP3 + ac1;

    uint32_t sbase = (uint32_t)__cvta_generic_to_shared(gsm);
    uint32_t dA0 = (uint32_t)(ar0 * GLD + ac0) * 2;
    uint32_t dA1 = (uint32_t)(ar1 * GLD + ac1) * 2;
    uint32_t dB0 = (uint32_t)(GBM * GLD + ar0 * GLD + ac0) * 2;
    uint32_t dB1 = (uint32_t)(GBM * GLD + ar1 * GLD + ac1) * 2;

    int warp = tid >> 5, lane = tid & 31;
    int wm = warp & 1, wn = warp >> 1;
    int gid = lane >> 2, tig = lane & 3;

    float acc[4][4][4];
    #pragma unroll
    for (int i = 0; i < 4; i++)
        #pragma unroll
        for (int j = 0; j < 4; j++)
            #pragma unroll
            for (int k = 0; k < 4; k++) acc[i][j][k] = 0.f;

    const int ksteps = KP3 / GBK;   // 96

    auto issue = [&](int kt) {
        uint32_t sb = sbase + (uint32_t)((kt % GSTAGES) * GSTAGE_ELEMS * 2);
        int seg = kt >> 5;
        int aoff = ((seg == 2) ? HID : 0) + (kt & 31) * GBK;
        int boff = kt * GBK;
        cp16(sb + dA0, Ag0 + aoff);
        cp16(sb + dA1, Ag1 + aoff);
        cp16(sb + dB0, Bg0 + boff);
        cp16(sb + dB1, Bg1 + boff);
        asm volatile("cp.async.commit_group;\n" ::: "memory");
    };

    issue(0);
    issue(1);

    for (int kt = 0; kt < ksteps; kt++) {
        if (kt + 1 < ksteps) asm volatile("cp.async.wait_group 1;\n" ::: "memory");
        else                 asm volatile("cp.async.wait_group 0;\n" ::: "memory");
        __syncthreads();
        if (kt + 2 < ksteps) issue(kt + 2);

        const __nv_bfloat16* As = gsm + (kt % GSTAGES) * GSTAGE_ELEMS;
        const __nv_bfloat16* Bs = As + GBM * GLD;

        #pragma unroll
        for (int kk = 0; kk < 2; kk++) {
            int kb = kk * 16 + 2 * tig;
            unsigned af[4][4], bf[4][2];
            #pragma unroll
            for (int mi = 0; mi < 4; mi++) {
                const __nv_bfloat16* p = &As[(wm * 64 + mi * 16 + gid) * GLD + kb];
                af[mi][0] = *(const unsigned*)p;
                af[mi][1] = *(const unsigned*)(p + 8 * GLD);
                af[mi][2] = *(const unsigned*)(p + 8);
                af[mi][3] = *(const unsigned*)(p + 8 * GLD + 8);
            }
            #pragma unroll
            for (int ni = 0; ni < 4; ni++) {
                const __nv_bfloat16* p = &Bs[(wn * 32 + ni * 8 + gid) * GLD + kb];
                bf[ni][0] = *(const unsigned*)p;
                bf[ni][1] = *(const unsigned*)(p + 8);
            }
            #pragma unroll
            for (int mi = 0; mi < 4; mi++)
                #pragma unroll
                for (int ni = 0; ni < 4; ni++)
                    mma_bf16(acc[mi][ni], af[mi], bf[ni]);
        }
        // no trailing sync: stage kt+2 (written next iter) was last read at kt-1,
        // and the single barrier above already ordered that.
    }

    #pragma unroll
    for (int mi = 0; mi < 4; mi++) {
        int r0 = bm * GBM + wm * 64 + mi * 16 + gid;
        #pragma unroll
        for (int ni = 0; ni < 4; ni++) {
            int c0 = bn * GBN + wn * 32 + ni * 8 + 2 * tig;
            float bv0 = bias[c0], bv1 = bias[c0 + 1];
            float2 v0 = make_float2(acc[mi][ni][0] + bv0, acc[mi][ni][1] + bv1);
            float2 v1 = make_float2(acc[mi][ni][2] + bv0, acc[mi][ni][3] + bv1);
            *(float2*)&C[(size_t)r0 * N + c0] = v0;
            *(float2*)&C[(size_t)(r0 + 8) * N + c0] = v1;
        }
    }
}

// ---------------- persistent recurrent kernel (all 512 steps, one launch) ----------
// 128 blocks x 256 threads (two warp-groups split K). cp.async double-buffered A
// staging, one bar.sync per k-tile. W_hh resident in shared memory.
#define SLD 72      // 64 + 8 pad
#define NBLK 128
#define ABUF (64 * SLD)                 // one 64x64 staging array (elems)

__global__ __launch_bounds__(256, 1) void gru_persist_kernel(
    int layer, const float* __restrict__ w_hh, const float* __restrict__ bhh,
    float* __restrict__ yext, int use_ext)
{
    extern __shared__ __nv_bfloat16 sm[];
    // layout (bf16 elems):
    //   sA: [group][buf][h/l] -> 8 arrays of ABUF         (0 .. 8*ABUF)
    //   sWh: 16*24*SLD   sWl: 16*24*SLD                   (8*ABUF ..)
    //   redbuf (float, 128*13)                            (after W)
    int tid = threadIdx.x;
    int group = tid >> 7;              // 0 or 1 (K halves)
    int gtid = tid & 127;
    int warp = tid >> 5;
    int wg = warp & 3;                 // warp within group
    int lane = tid & 31;
    int gid = lane >> 2, tig = lane & 3;
    int j0 = blockIdx.x * 8;

    __nv_bfloat16* sA = sm + group * 4 * ABUF;   // this group's 4 arrays [buf][h/l]
    __nv_bfloat16* sWh = sm + 8 * ABUF;
    __nv_bfloat16* sWl = sWh + 16 * 24 * SLD;
    float* redbuf = (float*)(sWl + 16 * 24 * SLD);

    uint32_t sAbase = (uint32_t)__cvta_generic_to_shared(sA);

    float* hprev = g_hprev[layer];
    float* yout  = use_ext ? yext : g_y0;

    // ---- one-time: load + split this block's 24 W_hh rows into smem ----
    for (int idx = tid; idx < 24 * 256; idx += 256) {
        int r = idx >> 8;            // 0..23
        int q = idx & 255;
        int grow = (r >> 3) * HID + j0 + (r & 7);
        const float* src = w_hh + (size_t)grow * HID + q * 4;
        float4 v = *(const float4*)src;
        float vv[4] = {v.x, v.y, v.z, v.w};
        __nv_bfloat16 hi[4], lo[4];
        #pragma unroll
        for (int e = 0; e < 4; e++) {
            hi[e] = __float2bfloat16(vv[e]);
            lo[e] = __float2bfloat16(vv[e] - __bfloat162float(hi[e]));
        }
        int col = q * 4;
        int kt = col >> 6;
        int c = col & 63;
        __nv_bfloat16* dh = sWh + kt * 24 * SLD + r * SLD + c;
        __nv_bfloat16* dl = sWl + kt * 24 * SLD + r * SLD + c;
        dh[0] = hi[0]; dh[1] = hi[1]; dh[2] = hi[2]; dh[3] = hi[3];
        dl[0] = lo[0]; dl[1] = lo[1]; dl[2] = lo[2]; dl[3] = lo[3];
    }
    __syncthreads();

    // A staging slots: 64x64 chunk = 512 uint4 slots, 4 per (group-local) thread
    int as_r[4], as_c[4];
    uint32_t sslot[4];
    #pragma unroll
    for (int i = 0; i < 4; i++) {
        int s = gtid + i * 128;
        as_r[i] = s >> 3; as_c[i] = (s & 7) << 3;
        sslot[i] = (uint32_t)(as_r[i] * SLD + as_c[i]) * 2;
    }
    const int kbase = group * 512;     // this group's K offset
    const int ktg0 = group * 8;

    // per-thread persistent state (group 0 owns gates/outputs)
    int jj0 = j0 + 2 * tig;
    float hb[3][2];
    float hreg[4];
    if (group == 0) {
        #pragma unroll
        for (int g = 0; g < 3; g++) {
            hb[g][0] = bhh[g * HID + jj0];
            hb[g][1] = bhh[g * HID + jj0 + 1];
        }
        #pragma unroll
        for (int ii = 0; ii < 4; ii++) {
            int b = wg * 16 + gid + ((ii >> 1) << 3);
            int j = jj0 + (ii & 1);
            hreg[ii] = hprev[b * HID + j];
        }
    }

    unsigned* bar = &g_barrier[layer];
    int barid = group + 1;

    for (int t = 0; t < SEQT; t++) {
        const __nv_bfloat16* Hs  = g_hs[t & 1];
        __nv_bfloat16*       Hso = g_hs[(t + 1) & 1];

        const __nv_bfloat16* Ar[4];
        #pragma unroll
        for (int i = 0; i < 4; i++)
            Ar[i] = Hs + (size_t)as_r[i] * KP2 + kbase + as_c[i];

        // prefetch input-gate preactivations early (DRAM latency hidden by GEMM)
        float xr[3][4];
        if (group == 0) {
            #pragma unroll
            for (int ii = 0; ii < 4; ii++) {
                int b = wg * 16 + gid + ((ii >> 1) << 3);
                int j = jj0 + (ii & 1);
                const float* xgp = g_xg + ((size_t)b * SEQT + t) * G3 + j;
                xr[0][ii] = xgp[0];
                xr[1][ii] = xgp[HID];
                xr[2][ii] = xgp[2 * HID];
            }
        }

        float acc[3][4];
        #pragma unroll
        for (int g = 0; g < 3; g++)
            #pragma unroll
            for (int k = 0; k < 4; k++) acc[g][k] = 0.f;

        auto issueA = [&](int kt) {
            uint32_t sb = sAbase + (uint32_t)((kt & 1) * 2 * ABUF * 2);
            int off = kt * 64;
            #pragma unroll
            for (int i = 0; i < 4; i++) {
                cp16(sb + sslot[i], Ar[i] + off);
                cp16(sb + (uint32_t)(ABUF * 2) + sslot[i], Ar[i] + HID + off);
            }
            asm volatile("cp.async.commit_group;\n" ::: "memory");
        };

        issueA(0);

        for (int kt = 0; kt < 8; kt++) {
            asm volatile("cp.async.wait_group 0;\n" ::: "memory");
            asm volatile("bar.sync %0, %1;\n" :: "r"(barid), "r"(128) : "memory");
            if (kt < 7) issueA(kt + 1);

            const __nv_bfloat16* bAh = sA + (kt & 1) * 2 * ABUF;
            const __nv_bfloat16* bAl = bAh + ABUF;
            const __nv_bfloat16* wh = sWh + (ktg0 + kt) * 24 * SLD;
            const __nv_bfloat16* wl = sWl + (ktg0 + kt) * 24 * SLD;
            #pragma unroll
            for (int kk = 0; kk < 4; kk++) {
                int kb = kk * 16 + 2 * tig;
                unsigned ah[4], al[4];
                const __nv_bfloat16* p = &bAh[(wg * 16 + gid) * SLD + kb];
                ah[0] = *(const unsigned*)p;
                ah[1] = *(const unsigned*)(p + 8 * SLD);
                ah[2] = *(const unsigned*)(p + 8);
                ah[3] = *(const unsigned*)(p + 8 * SLD + 8);
                const __nv_bfloat16* q = &bAl[(wg * 16 + gid) * SLD + kb];
                al[0] = *(const unsigned*)q;
                al[1] = *(const unsigned*)(q + 8 * SLD);
                al[2] = *(const unsigned*)(q + 8);
                al[3] = *(const unsigned*)(q + 8 * SLD + 8);
                #pragma unroll
                for (int g = 0; g < 3; g++) {
                    unsigned bh[2], bl[2];
                    const __nv_bfloat16* r = &wh[(g * 8 + gid) * SLD + kb];
                    bh[0] = *(const unsigned*)r; bh[1] = *(const unsigned*)(r + 8);
                    const __nv_bfloat16* s = &wl[(g * 8 + gid) * SLD + kb];
                    bl[0] = *(const unsigned*)s; bl[1] = *(const unsigned*)(s + 8);
                    mma_bf16(acc[g], ah, bh);
                    mma_bf16(acc[g], ah, bl);
                    mma_bf16(acc[g], al, bh);
                }
            }
            // single barrier per kt: next iteration's bar orders buffer reuse
        }

        // group barrier before cross-group reduction: ensure group's MMA done
        asm volatile("bar.sync %0, %1;\n" :: "r"(barid), "r"(128) : "memory");

        // cross-group K reduction
        if (group == 1) {
            #pragma unroll
            for (int g = 0; g < 3; g++)
                #pragma unroll
                for (int ii = 0; ii < 4; ii++)
                    redbuf[gtid * 13 + g * 4 + ii] = acc[g][ii];
        }
        __syncthreads();

        if (group == 0) {
            #pragma unroll
            for (int g = 0; g < 3; g++)
                #pragma unroll
                for (int ii = 0; ii < 4; ii++)
                    acc[g][ii] += redbuf[gtid * 13 + g * 4 + ii];

            #pragma unroll
            for (int ii = 0; ii < 4; ii++) {
                int b = wg * 16 + gid + ((ii >> 1) << 3);
                int j = jj0 + (ii & 1);
                int e = ii & 1;
                float pr = xr[0][ii] + acc[0][ii] + hb[0][e];
                float pz = xr[1][ii] + acc[1][ii] + hb[1][e];
                float pn = xr[2][ii];
                float r = __fdividef(1.f, 1.f + __expf(-pr));
                float z = __fdividef(1.f, 1.f + __expf(-pz));
                float a = pn + r * (acc[2][ii] + hb[2][e]);
                float n = 1.f - __fdividef(2.f, __expf(2.f * a) + 1.f);
                float h = (1.f - z) * n + z * hreg[ii];
                hreg[ii] = h;
                yout[((size_t)b * SEQT + t) * HID + j] = h;
                if (t == SEQT - 1) hprev[b * HID + j] = h;
                __nv_bfloat16 hi = __float2bfloat16(h);
                __nv_bfloat16 lo = __float2bfloat16(h - __bfloat162float(hi));
                Hso[b * KP2 + j] = hi;
                Hso[b * KP2 + HID + j] = lo;
            }
        }
        __syncthreads();

        // ---- device-wide step barrier (monotonic counter, release/acquire) ----
        if (tid == 0) {
            unsigned tgt = (unsigned)(t + 1) * NBLK;
            asm volatile("red.release.gpu.global.add.u32 [%0], %1;"
                         :: "l"(bar), "r"(1u) : "memory");
            unsigned v;
            do {
                asm volatile("ld.acquire.gpu.global.u32 %0, [%1];"
                             : "=r"(v) : "l"(bar) : "memory");
            } while (v < tgt);
        }
        __syncthreads();
    }
}

// ---------------- launch ----------------
extern "C" void kernel_launch(void* const* d_in, const int* in_sizes, int n_in,
                              void* d_out, int out_size)
{
    const float* x      = (const float*)d_in[0];
    const float* hidden = (const float*)d_in[1];
    const float* w_ih0  = (const float*)d_in[2];
    const float* w_hh0  = (const float*)d_in[3];
    const float* b_ih0  = (const float*)d_in[4];
    const float* b_hh0  = (const float*)d_in[5];
    const float* w_ih1  = (const float*)d_in[6];
    const float* w_hh1  = (const float*)d_in[7];
    const float* b_ih1  = (const float*)d_in[8];
    const float* b_hh1  = (const float*)d_in[9];
    float* out = (float*)d_out;

    const int persist_smem =
        (8 * ABUF + 2 * 16 * 24 * SLD) * (int)sizeof(__nv_bfloat16)   // A + W
        + 128 * 13 * (int)sizeof(float);                               // redbuf
    cudaFuncSetAttribute(gru_persist_kernel,
                         cudaFuncAttributeMaxDynamicSharedMemorySize, persist_smem);
    const int gemm_smem = GSTAGES * GSTAGE_ELEMS * (int)sizeof(__nv_bfloat16);  // 61440
    cudaFuncSetAttribute(gemm_big_kernel,
                         cudaFuncAttributeMaxDynamicSharedMemorySize, gemm_smem);

    // input-projection weight splits
    split3w_kernel<<<1024, 256>>>(w_ih0, 1);
    split3w_kernel<<<1024, 256>>>(w_ih1, 2);

    // ----- layer 0 -----
    split2a_kernel<<<4096, 256>>>(x, 0);
    gemm_big_kernel<<<dim3(G3 / GBN, MROWS / GBM), 256, gemm_smem>>>(0, b_ih0);
    hinit_kernel<<<256, 256>>>(hidden, 0);
    gru_persist_kernel<<<NBLK, 256, persist_smem>>>(0, w_hh0, b_hh0, nullptr, 0);

    // ----- layer 1 -----
    split2a_kernel<<<4096, 256>>>(nullptr, 1);
    gemm_big_kernel<<<dim3(G3 / GBN, MROWS / GBM), 256, gemm_smem>>>(1, b_ih1);
    hinit_kernel<<<256, 256>>>(hidden + BATCH * HID, 1);
    gru_persist_kernel<<<NBLK, 256, persist_smem>>>(1, w_hh1, b_hh1, out, 1);

    // final hidden states [2,B,H] appended after y1 (if the output carries them)
    if (out_size >= MROWS * HID + 2 * BATCH * HID)
        tail_kernel<<<512, 256>>>(out + (size_t)MROWS * HID);
}

// round 15
// speedup vs baseline: 1.0050x; 1.0050x over previous
#include <cuda_runtime.h>
#include <cuda_bf16.h>
#include <cstdint>

#define BATCH 64
#define SEQT  512
#define HID   1024
#define G3    3072            // 3*H
#define MROWS 32768           // B*T
#define KP3   3072            // 3*K split-concat (weights, big GEMM B operand)
#define KP2   2048            // 2*K split (activations + recurrent hidden)

// ---------------- device scratch (no allocations allowed) ----------------
__device__ __nv_bfloat16 g_Abig[(size_t)MROWS * KP2];   // split activations [hi|lo]
__device__ __nv_bfloat16 g_Wih0s[(size_t)G3 * KP3];
__device__ __nv_bfloat16 g_Wih1s[(size_t)G3 * KP3];
__device__ float         g_xg[(size_t)MROWS * G3];      // input-gate preactivations
__device__ float         g_y0[(size_t)MROWS * HID];     // layer0 outputs
__device__ float         g_hprev[2][BATCH * HID];
__device__ __nv_bfloat16 g_hs[2][BATCH * KP2];          // ping-pong split hidden
__device__ unsigned      g_barrier[2];                  // per-layer step barrier

// ---------------- helpers ----------------
__device__ __forceinline__ void mma_bf16(float c[4], const unsigned a[4], const unsigned b[2]) {
    asm volatile(
        "mma.sync.aligned.m16n8k16.row.col.f32.bf16.bf16.f32 "
        "{%0,%1,%2,%3}, {%4,%5,%6,%7}, {%8,%9}, {%0,%1,%2,%3};\n"
        : "+f"(c[0]), "+f"(c[1]), "+f"(c[2]), "+f"(c[3])
        : "r"(a[0]), "r"(a[1]), "r"(a[2]), "r"(a[3]), "r"(b[0]), "r"(b[1]));
}

__device__ __forceinline__ void cp16(uint32_t saddr, const void* gptr) {
    asm volatile("cp.async.cg.shared.global [%0], [%1], 16;\n"
                 :: "r"(saddr), "l"(gptr));
}

// activations: out = [hi | lo] (2048-wide) into g_Abig. use_y0: read g_y0.
__global__ void split2a_kernel(const float* __restrict__ src, int use_y0)
{
    const float* in = use_y0 ? g_y0 : src;
    int total = MROWS * HID;
    for (int i = blockIdx.x * blockDim.x + threadIdx.x; i < total;
         i += gridDim.x * blockDim.x) {
        int r = i >> 10;
        int c = i & 1023;
        float v = in[i];
        __nv_bfloat16 hi = __float2bfloat16(v);
        __nv_bfloat16 lo = __float2bfloat16(v - __bfloat162float(hi));
        __nv_bfloat16* o = g_Abig + (size_t)r * KP2;
        o[c] = hi; o[HID + c] = lo;
    }
}

// weights: out = [hi | lo | hi] (3072-wide). dst_sel: 1 -> g_Wih0s, 2 -> g_Wih1s.
__global__ void split3w_kernel(const float* __restrict__ src, int dst_sel)
{
    __nv_bfloat16* out = (dst_sel == 1) ? g_Wih0s : g_Wih1s;
    int total = G3 * HID;
    for (int i = blockIdx.x * blockDim.x + threadIdx.x; i < total;
         i += gridDim.x * blockDim.x) {
        int r = i >> 10;
        int c = i & 1023;
        float v = src[i];
        __nv_bfloat16 hi = __float2bfloat16(v);
        __nv_bfloat16 lo = __float2bfloat16(v - __bfloat162float(hi));
        __nv_bfloat16* o = out + (size_t)r * KP3;
        o[c] = hi; o[HID + c] = lo; o[2 * HID + c] = hi;
    }
}

__global__ void hinit_kernel(const float* __restrict__ h0, int layer)
{
    if (blockIdx.x == 0 && threadIdx.x == 0) g_barrier[layer] = 0;
    int i = blockIdx.x * blockDim.x + threadIdx.x;
    if (i < BATCH * HID) {
        float v = h0[i];
        g_hprev[layer][i] = v;
        __nv_bfloat16 hi = __float2bfloat16(v);
        __nv_bfloat16 lo = __float2bfloat16(v - __bfloat162float(hi));
        int b = i >> 10, j = i & 1023;
        g_hs[0][b * KP2 + j] = hi;
        g_hs[0][b * KP2 + HID + j] = lo;
    }
}

__global__ void tail_kernel(float* __restrict__ out)
{
    int i = blockIdx.x * blockDim.x + threadIdx.x;
    if (i < 2 * BATCH * HID) {
        int layer = i / (BATCH * HID);
        int r = i - layer * (BATCH * HID);
        out[i] = g_hprev[layer][r];
    }
}

// ---------------- big GEMM: g_xg = A'[M,3K] * W'[N,3K]^T + bias ----------------
// A' is virtual: seg0,1 -> hi (cols 0..1023 of g_Abig), seg2 -> lo (cols 1024..2047)
#define GBM 128
#define GBN 128
#define GBK 32
#define GLD 40      // BK + 8 bf16 pad (conflict-free, 16B-aligned rows)
#define GSTAGES 3
#define GSTAGE_ELEMS ((GBM + GBN) * GLD)   // 10240 bf16 per stage

__global__ __launch_bounds__(256, 2) void gemm_big_kernel(int wsel, const float* __restrict__ bias)
{
    extern __shared__ __nv_bfloat16 gsm[];
    const __nv_bfloat16* A = g_Abig;
    const __nv_bfloat16* B = wsel ? g_Wih1s : g_Wih0s;
    float* C = g_xg;
    const int N = G3;

    int tid = threadIdx.x;
    int bn = blockIdx.x, bm = blockIdx.y;

    int s0 = tid, s1 = tid + 256;
    int ar0 = s0 >> 2, ac0 = (s0 & 3) << 3;
    int ar1 = s1 >> 2, ac1 = (s1 & 3) << 3;

    const __nv_bfloat16* Ag0 = A + (size_t)(bm * GBM + ar0) * KP2 + ac0;
    const __nv_bfloat16* Ag1 = A + (size_t)(bm * GBM + ar1) * KP2 + ac1;
    const __nv_bfloat16* Bg0 = B + (size_t)(bn * GBN + ar0) * KP3 + ac0;
    const __nv_bfloat16* Bg1 = B + (size_t)(bn * GBN + ar1) * KP3 + ac1;

    uint32_t sbase = (uint32_t)__cvta_generic_to_shared(gsm);
    uint32_t dA0 = (uint32_t)(ar0 * GLD + ac0) * 2;
    uint32_t dA1 = (uint32_t)(ar1 * GLD + ac1) * 2;
    uint32_t dB0 = (uint32_t)(GBM * GLD + ar0 * GLD + ac0) * 2;
    uint32_t dB1 = (uint32_t)(GBM * GLD + ar1 * GLD + ac1) * 2;

    int warp = tid >> 5, lane = tid & 31;
    int wm = warp & 1, wn = warp >> 1;
    int gid = lane >> 2, tig = lane & 3;

    float acc[4][4][4];
    #pragma unroll
    for (int i = 0; i < 4; i++)
        #pragma unroll
        for (int j = 0; j < 4; j++)
            #pragma unroll
            for (int k = 0; k < 4; k++) acc[i][j][k] = 0.f;

    const int ksteps = KP3 / GBK;   // 96

    auto issue = [&](int kt) {
        uint32_t sb = sbase + (uint32_t)((kt % GSTAGES) * GSTAGE_ELEMS * 2);
        int seg = kt >> 5;
        int aoff = ((seg == 2) ? HID : 0) + (kt & 31) * GBK;
        int boff = kt * GBK;
        cp16(sb + dA0, Ag0 + aoff);
        cp16(sb + dA1, Ag1 + aoff);
        cp16(sb + dB0, Bg0 + boff);
        cp16(sb + dB1, Bg1 + boff);
        asm volatile("cp.async.commit_group;\n" ::: "memory");
    };

    issue(0);
    issue(1);

    for (int kt = 0; kt < ksteps; kt++) {
        if (kt + 1 < ksteps) asm volatile("cp.async.wait_group 1;\n" ::: "memory");
        else                 asm volatile("cp.async.wait_group 0;\n" ::: "memory");
        __syncthreads();
        if (kt + 2 < ksteps) issue(kt + 2);

        const __nv_bfloat16* As = gsm + (kt % GSTAGES) * GSTAGE_ELEMS;
        const __nv_bfloat16* Bs = As + GBM * GLD;

        #pragma unroll
        for (int kk = 0; kk < 2; kk++) {
            int kb = kk * 16 + 2 * tig;
            unsigned af[4][4], bf[4][2];
            #pragma unroll
            for (int mi = 0; mi < 4; mi++) {
                const __nv_bfloat16* p = &As[(wm * 64 + mi * 16 + gid) * GLD + kb];
                af[mi][0] = *(const unsigned*)p;
                af[mi][1] = *(const unsigned*)(p + 8 * GLD);
                af[mi][2] = *(const unsigned*)(p + 8);
                af[mi][3] = *(const unsigned*)(p + 8 * GLD + 8);
            }
            #pragma unroll
            for (int ni = 0; ni < 4; ni++) {
                const __nv_bfloat16* p = &Bs[(wn * 32 + ni * 8 + gid) * GLD + kb];
                bf[ni][0] = *(const unsigned*)p;
                bf[ni][1] = *(const unsigned*)(p + 8);
            }
            #pragma unroll
            for (int mi = 0; mi < 4; mi++)
                #pragma unroll
                for (int ni = 0; ni < 4; ni++)
                    mma_bf16(acc[mi][ni], af[mi], bf[ni]);
        }
        // no trailing sync: stage kt+2 (written next iter) was last read at kt-1,
        // and the single barrier above already ordered that.
    }

    #pragma unroll
    for (int mi = 0; mi < 4; mi++) {
        int r0 = bm * GBM + wm * 64 + mi * 16 + gid;
        #pragma unroll
        for (int ni = 0; ni < 4; ni++) {
            int c0 = bn * GBN + wn * 32 + ni * 8 + 2 * tig;
            float bv0 = bias[c0], bv1 = bias[c0 + 1];
            float2 v0 = make_float2(acc[mi][ni][0] + bv0, acc[mi][ni][1] + bv1);
            float2 v1 = make_float2(acc[mi][ni][2] + bv0, acc[mi][ni][3] + bv1);
            *(float2*)&C[(size_t)r0 * N + c0] = v0;
            *(float2*)&C[(size_t)(r0 + 8) * N + c0] = v1;
        }
    }
}

// ---------------- persistent recurrent kernel (all 512 steps, one launch) ----------
// 128 blocks x 256 threads (two warp-groups split K). cp.async double-buffered A
// staging, one bar.sync per k-tile. W_hh resident in shared memory.
#define SLD 72      // 64 + 8 pad
#define NBLK 128
#define ABUF (64 * SLD)                 // one 64x64 staging array (elems)

__global__ __launch_bounds__(256, 1) void gru_persist_kernel(
    int layer, const float* __restrict__ w_hh, const float* __restrict__ bhh,
    float* __restrict__ yext, int use_ext)
{
    extern __shared__ __nv_bfloat16 sm[];
    // layout (bf16 elems):
    //   sA: [group][buf][h/l] -> 8 arrays of ABUF         (0 .. 8*ABUF)
    //   sWh: 16*24*SLD   sWl: 16*24*SLD                   (8*ABUF ..)
    //   redbuf (float, 128*13)                            (after W)
    int tid = threadIdx.x;
    int group = tid >> 7;              // 0 or 1 (K halves)
    int gtid = tid & 127;
    int warp = tid >> 5;
    int wg = warp & 3;                 // warp within group
    int lane = tid & 31;
    int gid = lane >> 2, tig = lane & 3;
    int j0 = blockIdx.x * 8;

    __nv_bfloat16* sA = sm + group * 4 * ABUF;   // this group's 4 arrays [buf][h/l]
    __nv_bfloat16* sWh = sm + 8 * ABUF;
    __nv_bfloat16* sWl = sWh + 16 * 24 * SLD;
    float* redbuf = (float*)(sWl + 16 * 24 * SLD);

    uint32_t sAbase = (uint32_t)__cvta_generic_to_shared(sA);

    float* hprev = g_hprev[layer];
    float* yout  = use_ext ? yext : g_y0;

    // ---- one-time: load + split this block's 24 W_hh rows into smem ----
    for (int idx = tid; idx < 24 * 256; idx += 256) {
        int r = idx >> 8;            // 0..23
        int q = idx & 255;
        int grow = (r >> 3) * HID + j0 + (r & 7);
        const float* src = w_hh + (size_t)grow * HID + q * 4;
        float4 v = *(const float4*)src;
        float vv[4] = {v.x, v.y, v.z, v.w};
        __nv_bfloat16 hi[4], lo[4];
        #pragma unroll
        for (int e = 0; e < 4; e++) {
            hi[e] = __float2bfloat16(vv[e]);
            lo[e] = __float2bfloat16(vv[e] - __bfloat162float(hi[e]));
        }
        int col = q * 4;
        int kt = col >> 6;
        int c = col & 63;
        __nv_bfloat16* dh = sWh + kt * 24 * SLD + r * SLD + c;
        __nv_bfloat16* dl = sWl + kt * 24 * SLD + r * SLD + c;
        dh[0] = hi[0]; dh[1] = hi[1]; dh[2] = hi[2]; dh[3] = hi[3];
        dl[0] = lo[0]; dl[1] = lo[1]; dl[2] = lo[2]; dl[3] = lo[3];
    }
    __syncthreads();

    // A staging slots: 64x64 chunk = 512 uint4 slots, 4 per (group-local) thread
    int as_r[4], as_c[4];
    uint32_t sslot[4];
    #pragma unroll
    for (int i = 0; i < 4; i++) {
        int s = gtid + i * 128;
        as_r[i] = s >> 3; as_c[i] = (s & 7) << 3;
        sslot[i] = (uint32_t)(as_r[i] * SLD + as_c[i]) * 2;
    }
    const int kbase = group * 512;     // this group's K offset
    const int ktg0 = group * 8;

    // per-thread persistent state (group 0 owns gates/outputs)
    int jj0 = j0 + 2 * tig;
    float hb[3][2];
    float hreg[4];
    if (group == 0) {
        #pragma unroll
        for (int g = 0; g < 3; g++) {
            hb[g][0] = bhh[g * HID + jj0];
            hb[g][1] = bhh[g * HID + jj0 + 1];
        }
        #pragma unroll
        for (int ii = 0; ii < 4; ii++) {
            int b = wg * 16 + gid + ((ii >> 1) << 3);
            int j = jj0 + (ii & 1);
            hreg[ii] = hprev[b * HID + j];
        }
    }

    unsigned* bar = &g_barrier[layer];
    int barid = group + 1;

    for (int t = 0; t < SEQT; t++) {
        const __nv_bfloat16* Hs  = g_hs[t & 1];
        __nv_bfloat16*       Hso = g_hs[(t + 1) & 1];

        const __nv_bfloat16* Ar[4];
        #pragma unroll
        for (int i = 0; i < 4; i++)
            Ar[i] = Hs + (size_t)as_r[i] * KP2 + kbase + as_c[i];

        // prefetch input-gate preactivations early (DRAM latency hidden by GEMM)
        float xr[3][4];
        if (group == 0) {
            #pragma unroll
            for (int ii = 0; ii < 4; ii++) {
                int b = wg * 16 + gid + ((ii >> 1) << 3);
                int j = jj0 + (ii & 1);
                const float* xgp = g_xg + ((size_t)b * SEQT + t) * G3 + j;
                xr[0][ii] = xgp[0];
                xr[1][ii] = xgp[HID];
                xr[2][ii] = xgp[2 * HID];
            }
        }

        float acc[3][4];
        #pragma unroll
        for (int g = 0; g < 3; g++)
            #pragma unroll
            for (int k = 0; k < 4; k++) acc[g][k] = 0.f;

        auto issueA = [&](int kt) {
            uint32_t sb = sAbase + (uint32_t)((kt & 1) * 2 * ABUF * 2);
            int off = kt * 64;
            #pragma unroll
            for (int i = 0; i < 4; i++) {
                cp16(sb + sslot[i], Ar[i] + off);
                cp16(sb + (uint32_t)(ABUF * 2) + sslot[i], Ar[i] + HID + off);
            }
            asm volatile("cp.async.commit_group;\n" ::: "memory");
        };

        issueA(0);

        for (int kt = 0; kt < 8; kt++) {
            asm volatile("cp.async.wait_group 0;\n" ::: "memory");
            asm volatile("bar.sync %0, %1;\n" :: "r"(barid), "r"(128) : "memory");
            if (kt < 7) issueA(kt + 1);

            const __nv_bfloat16* bAh = sA + (kt & 1) * 2 * ABUF;
            const __nv_bfloat16* bAl = bAh + ABUF;
            const __nv_bfloat16* wh = sWh + (ktg0 + kt) * 24 * SLD;
            const __nv_bfloat16* wl = sWl + (ktg0 + kt) * 24 * SLD;
            #pragma unroll
            for (int kk = 0; kk < 4; kk++) {
                int kb = kk * 16 + 2 * tig;
                unsigned ah[4], al[4];
                const __nv_bfloat16* p = &bAh[(wg * 16 + gid) * SLD + kb];
                ah[0] = *(const unsigned*)p;
                ah[1] = *(const unsigned*)(p + 8 * SLD);
                ah[2] = *(const unsigned*)(p + 8);
                ah[3] = *(const unsigned*)(p + 8 * SLD + 8);
                const __nv_bfloat16* q = &bAl[(wg * 16 + gid) * SLD + kb];
                al[0] = *(const unsigned*)q;
                al[1] = *(const unsigned*)(q + 8 * SLD);
                al[2] = *(const unsigned*)(q + 8);
                al[3] = *(const unsigned*)(q + 8 * SLD + 8);
                #pragma unroll
                for (int g = 0; g < 3; g++) {
                    unsigned bh[2], bl[2];
                    const __nv_bfloat16* r = &wh[(g * 8 + gid) * SLD + kb];
                    bh[0] = *(const unsigned*)r; bh[1] = *(const unsigned*)(r + 8);
                    const __nv_bfloat16* s = &wl[(g * 8 + gid) * SLD + kb];
                    bl[0] = *(const unsigned*)s; bl[1] = *(const unsigned*)(s + 8);
                    mma_bf16(acc[g], ah, bh);
                    mma_bf16(acc[g], ah, bl);
                    mma_bf16(acc[g], al, bh);
                }
            }
            // single barrier per kt: next iteration's bar orders buffer reuse
        }

        // group barrier before cross-group reduction: ensure group's MMA done
        asm volatile("bar.sync %0, %1;\n" :: "r"(barid), "r"(128) : "memory");

        // cross-group K reduction
        if (group == 1) {
            #pragma unroll
            for (int g = 0; g < 3; g++)
                #pragma unroll
                for (int ii = 0; ii < 4; ii++)
                    redbuf[gtid * 13 + g * 4 + ii] = acc[g][ii];
        }
        __syncthreads();

        if (group == 0) {
            #pragma unroll
            for (int g = 0; g < 3; g++)
                #pragma unroll
                for (int ii = 0; ii < 4; ii++)
                    acc[g][ii] += redbuf[gtid * 13 + g * 4 + ii];

            #pragma unroll
            for (int ii = 0; ii < 4; ii++) {
                int b = wg * 16 + gid + ((ii >> 1) << 3);
                int j = jj0 + (ii & 1);
                int e = ii & 1;
                float pr = xr[0][ii] + acc[0][ii] + hb[0][e];
                float pz = xr[1][ii] + acc[1][ii] + hb[1][e];
                float pn = xr[2][ii];
                float r = __fdividef(1.f, 1.f + __expf(-pr));
                float z = __fdividef(1.f, 1.f + __expf(-pz));
                float a = pn + r * (acc[2][ii] + hb[2][e]);
                float n = 1.f - __fdividef(2.f, __expf(2.f * a) + 1.f);
                float h = (1.f - z) * n + z * hreg[ii];
                hreg[ii] = h;
                yout[((size_t)b * SEQT + t) * HID + j] = h;
                if (t == SEQT - 1) hprev[b * HID + j] = h;
                __nv_bfloat16 hi = __float2bfloat16(h);
                __nv_bfloat16 lo = __float2bfloat16(h - __bfloat162float(hi));
                Hso[b * KP2 + j] = hi;
                Hso[b * KP2 + HID + j] = lo;
            }
        }
        __syncthreads();

        // ---- device-wide step barrier (monotonic counter, release/acquire) ----
        if (tid == 0) {
            unsigned tgt = (unsigned)(t + 1) * NBLK;
            asm volatile("red.release.gpu.global.add.u32 [%0], %1;"
                         :: "l"(bar), "r"(1u) : "memory");
            unsigned v;
            do {
                asm volatile("ld.acquire.gpu.global.u32 %0, [%1];"
                             : "=r"(v) : "l"(bar) : "memory");
            } while (v < tgt);
        }
        __syncthreads();
    }
}

// ---------------- launch ----------------
extern "C" void kernel_launch(void* const* d_in, const int* in_sizes, int n_in,
                              void* d_out, int out_size)
{
    const float* x      = (const float*)d_in[0];
    const float* hidden = (const float*)d_in[1];
    const float* w_ih0  = (const float*)d_in[2];
    const float* w_hh0  = (const float*)d_in[3];
    const float* b_ih0  = (const float*)d_in[4];
    const float* b_hh0  = (const float*)d_in[5];
    const float* w_ih1  = (const float*)d_in[6];
    const float* w_hh1  = (const float*)d_in[7];
    const float* b_ih1  = (const float*)d_in[8];
    const float* b_hh1  = (const float*)d_in[9];
    float* out = (float*)d_out;

    const int persist_smem =
        (8 * ABUF + 2 * 16 * 24 * SLD) * (int)sizeof(__nv_bfloat16)   // A + W
        + 128 * 13 * (int)sizeof(float);                               // redbuf
    cudaFuncSetAttribute(gru_persist_kernel,
                         cudaFuncAttributeMaxDynamicSharedMemorySize, persist_smem);
    const int gemm_smem = GSTAGES * GSTAGE_ELEMS * (int)sizeof(__nv_bfloat16);  // 61440
    cudaFuncSetAttribute(gemm_big_kernel,
                         cudaFuncAttributeMaxDynamicSharedMemorySize, gemm_smem);

    // input-projection weight splits
    split3w_kernel<<<1024, 256>>>(w_ih0, 1);
    split3w_kernel<<<1024, 256>>>(w_ih1, 2);

    // ----- layer 0 -----
    split2a_kernel<<<4096, 256>>>(x, 0);
    gemm_big_kernel<<<dim3(G3 / GBN, MROWS / GBM), 256, gemm_smem>>>(0, b_ih0);
    hinit_kernel<<<256, 256>>>(hidden, 0);
    gru_persist_kernel<<<NBLK, 256, persist_smem>>>(0, w_hh0, b_hh0, nullptr, 0);

    // ----- layer 1 -----
    split2a_kernel<<<4096, 256>>>(nullptr, 1);
    gemm_big_kernel<<<dim3(G3 / GBN, MROWS / GBM), 256, gemm_smem>>>(1, b_ih1);
    hinit_kernel<<<256, 256>>>(hidden + BATCH * HID, 1);
    gru_persist_kernel<<<NBLK, 256, persist_smem>>>(1, w_hh1, b_hh1, out, 1);

    // final hidden states [2,B,H] appended after y1 (if the output carries them)
    if (out_size >= MROWS * HID + 2 * BATCH * HID)
        tail_kernel<<<512, 256>>>(out + (size_t)MROWS * HID);
}

// round 16
// speedup vs baseline: 1.0305x; 1.0253x over previous
#include <cuda_runtime.h>
#include <cuda_bf16.h>
#include <cstdint>

#define BATCH 64
#define SEQT  512
#define HID   1024
#define G3    3072            // 3*H
#define MROWS 32768           // B*T
#define KP3   3072            // 3*K split-concat (weights, big GEMM B operand)
#define KP2   2048            // 2*K split (activations + recurrent hidden)

// ---------------- device scratch (no allocations allowed) ----------------
__device__ __nv_bfloat16 g_Abig[(size_t)MROWS * KP2];   // split activations [hi|lo]
__device__ __nv_bfloat16 g_Wih0s[(size_t)G3 * KP3];
__device__ __nv_bfloat16 g_Wih1s[(size_t)G3 * KP3];
__device__ float         g_xg[(size_t)MROWS * G3];      // input-gate preactivations
__device__ float         g_y0[(size_t)MROWS * HID];     // layer0 outputs
__device__ float         g_hprev[2][BATCH * HID];
__device__ __nv_bfloat16 g_hs[2][BATCH * KP2];          // ping-pong split hidden
__device__ unsigned      g_barrier[2];                  // per-layer step barrier

// ---------------- helpers ----------------
__device__ __forceinline__ void mma_bf16(float c[4], const unsigned a[4], const unsigned b[2]) {
    asm volatile(
        "mma.sync.aligned.m16n8k16.row.col.f32.bf16.bf16.f32 "
        "{%0,%1,%2,%3}, {%4,%5,%6,%7}, {%8,%9}, {%0,%1,%2,%3};\n"
        : "+f"(c[0]), "+f"(c[1]), "+f"(c[2]), "+f"(c[3])
        : "r"(a[0]), "r"(a[1]), "r"(a[2]), "r"(a[3]), "r"(b[0]), "r"(b[1]));
}

__device__ __forceinline__ void cp16(uint32_t saddr, const void* gptr) {
    asm volatile("cp.async.cg.shared.global [%0], [%1], 16;\n"
                 :: "r"(saddr), "l"(gptr));
}

// activations: out = [hi | lo] (2048-wide) into g_Abig. use_y0: read g_y0.
__global__ void split2a_kernel(const float* __restrict__ src, int use_y0)
{
    const float* in = use_y0 ? g_y0 : src;
    int total = MROWS * HID;
    for (int i = blockIdx.x * blockDim.x + threadIdx.x; i < total;
         i += gridDim.x * blockDim.x) {
        int r = i >> 10;
        int c = i & 1023;
        float v = in[i];
        __nv_bfloat16 hi = __float2bfloat16(v);
        __nv_bfloat16 lo = __float2bfloat16(v - __bfloat162float(hi));
        __nv_bfloat16* o = g_Abig + (size_t)r * KP2;
        o[c] = hi; o[HID + c] = lo;
    }
}

// weights: out = [hi | lo | hi] (3072-wide). dst_sel: 1 -> g_Wih0s, 2 -> g_Wih1s.
__global__ void split3w_kernel(const float* __restrict__ src, int dst_sel)
{
    __nv_bfloat16* out = (dst_sel == 1) ? g_Wih0s : g_Wih1s;
    int total = G3 * HID;
    for (int i = blockIdx.x * blockDim.x + threadIdx.x; i < total;
         i += gridDim.x * blockDim.x) {
        int r = i >> 10;
        int c = i & 1023;
        float v = src[i];
        __nv_bfloat16 hi = __float2bfloat16(v);
        __nv_bfloat16 lo = __float2bfloat16(v - __bfloat162float(hi));
        __nv_bfloat16* o = out + (size_t)r * KP3;
        o[c] = hi; o[HID + c] = lo; o[2 * HID + c] = hi;
    }
}

__global__ void hinit_kernel(const float* __restrict__ h0, int layer)
{
    if (blockIdx.x == 0 && threadIdx.x == 0) g_barrier[layer] = 0;
    int i = blockIdx.x * blockDim.x + threadIdx.x;
    if (i < BATCH * HID) {
        float v = h0[i];
        g_hprev[layer][i] = v;
        __nv_bfloat16 hi = __float2bfloat16(v);
        __nv_bfloat16 lo = __float2bfloat16(v - __bfloat162float(hi));
        int b = i >> 10, j = i & 1023;
        g_hs[0][b * KP2 + j] = hi;
        g_hs[0][b * KP2 + HID + j] = lo;
    }
}

__global__ void tail_kernel(float* __restrict__ out)
{
    int i = blockIdx.x * blockDim.x + threadIdx.x;
    if (i < 2 * BATCH * HID) {
        int layer = i / (BATCH * HID);
        int r = i - layer * (BATCH * HID);
        out[i] = g_hprev[layer][r];
    }
}

// ---------------- big GEMM: g_xg = A'[M,3K] * W'[N,3K]^T + bias ----------------
// A' is virtual: seg0,1 -> hi (cols 0..1023 of g_Abig), seg2 -> lo (cols 1024..2047)
#define GBM 128
#define GBN 128
#define GBK 32
#define GLD 40      // BK + 8 bf16 pad (conflict-free, 16B-aligned rows)
#define GSTAGES 3
#define GSTAGE_ELEMS ((GBM + GBN) * GLD)   // 10240 bf16 per stage

__global__ __launch_bounds__(256, 2) void gemm_big_kernel(int wsel, const float* __restrict__ bias)
{
    extern __shared__ __nv_bfloat16 gsm[];
    const __nv_bfloat16* A = g_Abig;
    const __nv_bfloat16* B = wsel ? g_Wih1s : g_Wih0s;
    float* C = g_xg;
    const int N = G3;

    int tid = threadIdx.x;
    int bn = blockIdx.x, bm = blockIdx.y;

    int s0 = tid, s1 = tid + 256;
    int ar0 = s0 >> 2, ac0 = (s0 & 3) << 3;
    int ar1 = s1 >> 2, ac1 = (s1 & 3) << 3;

    const __nv_bfloat16* Ag0 = A + (size_t)(bm * GBM + ar0) * KP2 + ac0;
    const __nv_bfloat16* Ag1 = A + (size_t)(bm * GBM + ar1) * KP2 + ac1;
    const __nv_bfloat16* Bg0 = B + (size_t)(bn * GBN + ar0) * KP3 + ac0;
    const __nv_bfloat16* Bg1 = B + (size_t)(bn * GBN + ar1) * KP3 + ac1;

    uint32_t sbase = (uint32_t)__cvta_generic_to_shared(gsm);
    uint32_t dA0 = (uint32_t)(ar0 * GLD + ac0) * 2;
    uint32_t dA1 = (uint32_t)(ar1 * GLD + ac1) * 2;
    uint32_t dB0 = (uint32_t)(GBM * GLD + ar0 * GLD + ac0) * 2;
    uint32_t dB1 = (uint32_t)(GBM * GLD + ar1 * GLD + ac1) * 2;

    int warp = tid >> 5, lane = tid & 31;
    int wm = warp & 1, wn = warp >> 1;
    int gid = lane >> 2, tig = lane & 3;

    float acc[4][4][4];
    #pragma unroll
    for (int i = 0; i < 4; i++)
        #pragma unroll
        for (int j = 0; j < 4; j++)
            #pragma unroll
            for (int k = 0; k < 4; k++) acc[i][j][k] = 0.f;

    const int ksteps = KP3 / GBK;   // 96

    auto issue = [&](int kt) {
        uint32_t sb = sbase + (uint32_t)((kt % GSTAGES) * GSTAGE_ELEMS * 2);
        int seg = kt >> 5;
        int aoff = ((seg == 2) ? HID : 0) + (kt & 31) * GBK;
        int boff = kt * GBK;
        cp16(sb + dA0, Ag0 + aoff);
        cp16(sb + dA1, Ag1 + aoff);
        cp16(sb + dB0, Bg0 + boff);
        cp16(sb + dB1, Bg1 + boff);
        asm volatile("cp.async.commit_group;\n" ::: "memory");
    };

    issue(0);
    issue(1);

    for (int kt = 0; kt < ksteps; kt++) {
        if (kt + 1 < ksteps) asm volatile("cp.async.wait_group 1;\n" ::: "memory");
        else                 asm volatile("cp.async.wait_group 0;\n" ::: "memory");
        __syncthreads();
        if (kt + 2 < ksteps) issue(kt + 2);

        const __nv_bfloat16* As = gsm + (kt % GSTAGES) * GSTAGE_ELEMS;
        const __nv_bfloat16* Bs = As + GBM * GLD;

        #pragma unroll
        for (int kk = 0; kk < 2; kk++) {
            int kb = kk * 16 + 2 * tig;
            unsigned af[4][4], bf[4][2];
            #pragma unroll
            for (int mi = 0; mi < 4; mi++) {
                const __nv_bfloat16* p = &As[(wm * 64 + mi * 16 + gid) * GLD + kb];
                af[mi][0] = *(const unsigned*)p;
                af[mi][1] = *(const unsigned*)(p + 8 * GLD);
                af[mi][2] = *(const unsigned*)(p + 8);
                af[mi][3] = *(const unsigned*)(p + 8 * GLD + 8);
            }
            #pragma unroll
            for (int ni = 0; ni < 4; ni++) {
                const __nv_bfloat16* p = &Bs[(wn * 32 + ni * 8 + gid) * GLD + kb];
                bf[ni][0] = *(const unsigned*)p;
                bf[ni][1] = *(const unsigned*)(p + 8);
            }
            #pragma unroll
            for (int mi = 0; mi < 4; mi++)
                #pragma unroll
                for (int ni = 0; ni < 4; ni++)
                    mma_bf16(acc[mi][ni], af[mi], bf[ni]);
        }
    }

    #pragma unroll
    for (int mi = 0; mi < 4; mi++) {
        int r0 = bm * GBM + wm * 64 + mi * 16 + gid;
        #pragma unroll
        for (int ni = 0; ni < 4; ni++) {
            int c0 = bn * GBN + wn * 32 + ni * 8 + 2 * tig;
            float bv0 = bias[c0], bv1 = bias[c0 + 1];
            float2 v0 = make_float2(acc[mi][ni][0] + bv0, acc[mi][ni][1] + bv1);
            float2 v1 = make_float2(acc[mi][ni][2] + bv0, acc[mi][ni][3] + bv1);
            *(float2*)&C[(size_t)r0 * N + c0] = v0;
            *(float2*)&C[(size_t)(r0 + 8) * N + c0] = v1;
        }
    }
}

// ---------------- persistent recurrent kernel (all 512 steps, one launch) ----------
// 128 blocks x 512 threads. 4 K-groups of 128 threads (K=256 each, 4 k-tiles of 64).
// Per-term split accumulators (9 independent MMA chains/warp). All 512 threads do
// the gate phase (1 output each). W_hh resident in smem. Grid barrier between steps.
#define SLD 72      // 64 + 8 pad  (36 words/row -> conflict-free 4-bank stride)
#define NBLK 128
#define NGRP 4
#define ABUF (64 * SLD)                 // one 64x64 staging array (elems)

__global__ __launch_bounds__(512, 1) void gru_persist_kernel(
    int layer, const float* __restrict__ w_hh, const float* __restrict__ bhh,
    float* __restrict__ yext, int use_ext)
{
    extern __shared__ __nv_bfloat16 sm[];
    // layout (bf16 elems):
    //   sA: [group][h/l] -> 8 arrays of ABUF            (0 .. 8*ABUF)
    //   sWh: 16*24*SLD   sWl: 16*24*SLD
    //   redbuf (float, NGRP*64*8*3 = 6144)
    int tid = threadIdx.x;
    int group = tid >> 7;              // 0..3 (K quarters)
    int gtid = tid & 127;
    int wg = (tid >> 5) & 3;           // warp within group
    int lane = tid & 31;
    int gid = lane >> 2, tig = lane & 3;
    int j0 = blockIdx.x * 8;

    __nv_bfloat16* sAh = sm + group * 2 * ABUF;
    __nv_bfloat16* sAl = sAh + ABUF;
    __nv_bfloat16* sWh = sm + 2 * NGRP * ABUF;
    __nv_bfloat16* sWl = sWh + 16 * 24 * SLD;
    float* redbuf = (float*)(sWl + 16 * 24 * SLD);   // [grp][b][jj][gate]

    float* hprev = g_hprev[layer];
    float* yout  = use_ext ? yext : g_y0;

    // ---- one-time: load + split this block's 24 W_hh rows into smem ----
    for (int idx = tid; idx < 24 * 256; idx += 512) {
        int r = idx >> 8;            // 0..23
        int q = idx & 255;
        int grow = (r >> 3) * HID + j0 + (r & 7);
        const float* src = w_hh + (size_t)grow * HID + q * 4;
        float4 v = *(const float4*)src;
        float vv[4] = {v.x, v.y, v.z, v.w};
        __nv_bfloat16 hi[4], lo[4];
        #pragma unroll
        for (int e = 0; e < 4; e++) {
            hi[e] = __float2bfloat16(vv[e]);
            lo[e] = __float2bfloat16(vv[e] - __bfloat162float(hi[e]));
        }
        int col = q * 4;
        int kt = col >> 6;
        int c = col & 63;
        __nv_bfloat16* dh = sWh + kt * 24 * SLD + r * SLD + c;
        __nv_bfloat16* dl = sWl + kt * 24 * SLD + r * SLD + c;
        dh[0] = hi[0]; dh[1] = hi[1]; dh[2] = hi[2]; dh[3] = hi[3];
        dl[0] = lo[0]; dl[1] = lo[1]; dl[2] = lo[2]; dl[3] = lo[3];
    }
    __syncthreads();

    // A staging slots: 64x64 chunk = 512 uint4 slots, 4 per (group-local) thread
    int as_r[4], as_c[4];
    #pragma unroll
    for (int i = 0; i < 4; i++) {
        int s = gtid + i * 128;
        as_r[i] = s >> 3; as_c[i] = (s & 7) << 3;
    }
    const int kbase = group * 256;     // this group's K offset
    const int ktg0 = group * 4;        // this group's global kt base

    // gate-phase ownership: one output point per thread
    int gb = tid >> 3;                 // batch 0..63
    int gj = j0 + (tid & 7);           // hidden column
    float hb0 = bhh[gj];
    float hb1 = bhh[HID + gj];
    float hb2 = bhh[2 * HID + gj];
    float hreg = hprev[gb * HID + gj];

    unsigned* bar = &g_barrier[layer];
    int barid = group + 1;

    for (int t = 0; t < SEQT; t++) {
        const __nv_bfloat16* Hs  = g_hs[t & 1];
        __nv_bfloat16*       Hso = g_hs[(t + 1) & 1];

        // prefetch input-gate preactivations (DRAM latency hidden under MMA)
        const float* xgp = g_xg + ((size_t)gb * SEQT + t) * G3 + gj;
        float xr0 = xgp[0];
        float xr1 = xgp[HID];
        float xr2 = xgp[2 * HID];

        const __nv_bfloat16* Ar[4];
        #pragma unroll
        for (int i = 0; i < 4; i++)
            Ar[i] = Hs + (size_t)as_r[i] * KP2 + kbase + as_c[i];

        // per-term accumulators: 9 independent MMA chains
        float a1[3][4], a2[3][4], a3[3][4];
        #pragma unroll
        for (int g = 0; g < 3; g++)
            #pragma unroll
            for (int k = 0; k < 4; k++) { a1[g][k] = 0.f; a2[g][k] = 0.f; a3[g][k] = 0.f; }

        uint4 pah[4], pal[4];
        #pragma unroll
        for (int i = 0; i < 4; i++) {
            pah[i] = *(const uint4*)(Ar[i]);
            pal[i] = *(const uint4*)(Ar[i] + HID);
        }

        for (int kt = 0; kt < 4; kt++) {
            #pragma unroll
            for (int i = 0; i < 4; i++) {
                *(uint4*)&sAh[as_r[i] * SLD + as_c[i]] = pah[i];
                *(uint4*)&sAl[as_r[i] * SLD + as_c[i]] = pal[i];
            }
            asm volatile("bar.sync %0, %1;\n" :: "r"(barid), "r"(128) : "memory");
            if (kt < 3) {
                int off = (kt + 1) * 64;
                #pragma unroll
                for (int i = 0; i < 4; i++) {
                    pah[i] = *(const uint4*)(Ar[i] + off);
                    pal[i] = *(const uint4*)(Ar[i] + HID + off);
                }
            }
            const __nv_bfloat16* wh = sWh + (ktg0 + kt) * 24 * SLD;
            const __nv_bfloat16* wl = sWl + (ktg0 + kt) * 24 * SLD;
            #pragma unroll
            for (int kk = 0; kk < 4; kk++) {
                int kb = kk * 16 + 2 * tig;
                unsigned ah[4], al[4];
                const __nv_bfloat16* p = &sAh[(wg * 16 + gid) * SLD + kb];
                ah[0] = *(const unsigned*)p;
                ah[1] = *(const unsigned*)(p + 8 * SLD);
                ah[2] = *(const unsigned*)(p + 8);
                ah[3] = *(const unsigned*)(p + 8 * SLD + 8);
                const __nv_bfloat16* q = &sAl[(wg * 16 + gid) * SLD + kb];
                al[0] = *(const unsigned*)q;
                al[1] = *(const unsigned*)(q + 8 * SLD);
                al[2] = *(const unsigned*)(q + 8);
                al[3] = *(const unsigned*)(q + 8 * SLD + 8);
                #pragma unroll
                for (int g = 0; g < 3; g++) {
                    unsigned bh[2], bl[2];
                    const __nv_bfloat16* r = &wh[(g * 8 + gid) * SLD + kb];
                    bh[0] = *(const unsigned*)r; bh[1] = *(const unsigned*)(r + 8);
                    const __nv_bfloat16* s = &wl[(g * 8 + gid) * SLD + kb];
                    bl[0] = *(const unsigned*)s; bl[1] = *(const unsigned*)(s + 8);
                    mma_bf16(a1[g], ah, bh);
                    mma_bf16(a2[g], ah, bl);
                    mma_bf16(a3[g], al, bh);
                }
            }
            asm volatile("bar.sync %0, %1;\n" :: "r"(barid), "r"(128) : "memory");
        }

        // write per-group partials: redbuf[((grp*64 + b)*8 + jj)*3 + gate]
        #pragma unroll
        for (int g = 0; g < 3; g++) {
            #pragma unroll
            for (int ii = 0; ii < 4; ii++) {
                int b = wg * 16 + gid + ((ii >> 1) << 3);
                int jj = 2 * tig + (ii & 1);
                redbuf[((group * 64 + b) * 8 + jj) * 3 + g] =
                    a1[g][ii] + a2[g][ii] + a3[g][ii];
            }
        }
        __syncthreads();

        // gate phase: every thread handles one (b, j) output
        {
            int bjj = (gb * 8 + (tid & 7)) * 3;
            float s0 = 0.f, s1 = 0.f, s2 = 0.f;
            #pragma unroll
            for (int g4 = 0; g4 < NGRP; g4++) {
                const float* rb = &redbuf[(g4 * 512) * 3 + bjj];
                s0 += rb[0]; s1 += rb[1]; s2 += rb[2];
            }
            float pr = xr0 + s0 + hb0;
            float pz = xr1 + s1 + hb1;
            float r = __fdividef(1.f, 1.f + __expf(-pr));
            float z = __fdividef(1.f, 1.f + __expf(-pz));
            float a = xr2 + r * (s2 + hb2);
            float n = 1.f - __fdividef(2.f, __expf(2.f * a) + 1.f);
            float h = (1.f - z) * n + z * hreg;
            hreg = h;
            yout[((size_t)gb * SEQT + t) * HID + gj] = h;
            if (t == SEQT - 1) hprev[gb * HID + gj] = h;
            __nv_bfloat16 hi = __float2bfloat16(h);
            __nv_bfloat16 lo = __float2bfloat16(h - __bfloat162float(hi));
            Hso[gb * KP2 + gj] = hi;
            Hso[gb * KP2 + HID + gj] = lo;
        }

        // ---- device-wide step barrier (monotonic counter, release/acquire) ----
        __syncthreads();
        if (tid == 0) {
            unsigned tgt = (unsigned)(t + 1) * NBLK;
            asm volatile("red.release.gpu.global.add.u32 [%0], %1;"
                         :: "l"(bar), "r"(1u) : "memory");
            unsigned v;
            do {
                asm volatile("ld.acquire.gpu.global.u32 %0, [%1];"
                             : "=r"(v) : "l"(bar) : "memory");
            } while (v < tgt);
        }
        __syncthreads();
    }
}

// ---------------- launch ----------------
extern "C" void kernel_launch(void* const* d_in, const int* in_sizes, int n_in,
                              void* d_out, int out_size)
{
    const float* x      = (const float*)d_in[0];
    const float* hidden = (const float*)d_in[1];
    const float* w_ih0  = (const float*)d_in[2];
    const float* w_hh0  = (const float*)d_in[3];
    const float* b_ih0  = (const float*)d_in[4];
    const float* b_hh0  = (const float*)d_in[5];
    const float* w_ih1  = (const float*)d_in[6];
    const float* w_hh1  = (const float*)d_in[7];
    const float* b_ih1  = (const float*)d_in[8];
    const float* b_hh1  = (const float*)d_in[9];
    float* out = (float*)d_out;

    const int persist_smem =
        (2 * NGRP * ABUF + 2 * 16 * 24 * SLD) * (int)sizeof(__nv_bfloat16)  // A + W
        + NGRP * 64 * 8 * 3 * (int)sizeof(float);                            // redbuf
    cudaFuncSetAttribute(gru_persist_kernel,
                         cudaFuncAttributeMaxDynamicSharedMemorySize, persist_smem);
    const int gemm_smem = GSTAGES * GSTAGE_ELEMS * (int)sizeof(__nv_bfloat16);  // 61440
    cudaFuncSetAttribute(gemm_big_kernel,
                         cudaFuncAttributeMaxDynamicSharedMemorySize, gemm_smem);

    // input-projection weight splits
    split3w_kernel<<<1024, 256>>>(w_ih0, 1);
    split3w_kernel<<<1024, 256>>>(w_ih1, 2);

    // ----- layer 0 -----
    split2a_kernel<<<4096, 256>>>(x, 0);
    gemm_big_kernel<<<dim3(G3 / GBN, MROWS / GBM), 256, gemm_smem>>>(0, b_ih0);
    hinit_kernel<<<256, 256>>>(hidden, 0);
    gru_persist_kernel<<<NBLK, 512, persist_smem>>>(0, w_hh0, b_hh0, nullptr, 0);

    // ----- layer 1 -----
    split2a_kernel<<<4096, 256>>>(nullptr, 1);
    gemm_big_kernel<<<dim3(G3 / GBN, MROWS / GBM), 256, gemm_smem>>>(1, b_ih1);
    hinit_kernel<<<256, 256>>>(hidden + BATCH * HID, 1);
    gru_persist_kernel<<<NBLK, 512, persist_smem>>>(1, w_hh1, b_hh1, out, 1);

    // final hidden states [2,B,H] appended after y1 (if the output carries them)
    if (out_size >= MROWS * HID + 2 * BATCH * HID)
        tail_kernel<<<512, 256>>>(out + (size_t)MROWS * HID);
}